// round 1
// baseline (speedup 1.0000x reference)
#include <cuda_runtime.h>
#include <cuda_bf16.h>
#include <math.h>

// Problem constants
#define TT   8192
#define KK   2
#define HH   1024
#define II   2816
#define EE   8
#define TKN  (TT*KK)        // 16384 assignments

#define TM   64
#define TN   64
#define BK   16
#define NT_MAX (TKN/TM + EE)   // 264 row tiles upper bound

// ---------------- device scratch (static globals; no cudaMalloc) -------------
__device__ int   g_counts[EE];
__device__ int   g_cursor[EE];
__device__ int   g_offsets[EE + 1];
__device__ int   g_slot_token[TKN];
__device__ float g_slot_weight[TKN];
__device__ int   g_tile_expert[NT_MAX];
__device__ int   g_tile_row[NT_MAX];
__device__ int   g_num_tiles;
__device__ float g_h[(size_t)TKN * II];   // 176 MB intermediate activations

// ---------------- routing ---------------------------------------------------
__global__ void k_init() {
    int t = threadIdx.x;
    if (t < EE) { g_counts[t] = 0; g_cursor[t] = 0; }
    if (t == 0) g_num_tiles = 0;
}

__global__ void k_zero_out(float* out) {
    size_t i = (size_t)blockIdx.x * blockDim.x + threadIdx.x;
    if (i < (size_t)TT * HH) out[i] = 0.0f;
}

__global__ void k_count(const int* __restrict__ routing) {
    int i = blockIdx.x * blockDim.x + threadIdx.x;
    if (i < TKN) atomicAdd(&g_counts[routing[i]], 1);
}

__global__ void k_scan() {
    // single thread; E=8 trivial
    int off = 0;
    for (int e = 0; e < EE; e++) { g_offsets[e] = off; off += g_counts[e]; }
    g_offsets[EE] = off;
    int nt = 0;
    for (int e = 0; e < EE; e++) {
        int ne = g_counts[e];
        for (int r = 0; r < ne; r += TM) {
            g_tile_expert[nt] = e;
            g_tile_row[nt]    = g_offsets[e] + r;
            nt++;
        }
    }
    g_num_tiles = nt;
}

__global__ void k_scatter(const int* __restrict__ routing,
                          const float* __restrict__ rweights) {
    int i = blockIdx.x * blockDim.x + threadIdx.x;
    if (i < TKN) {
        int e = routing[i];
        int pos = g_offsets[e] + atomicAdd(&g_cursor[e], 1);
        g_slot_token[pos]  = i / KK;      // token index
        g_slot_weight[pos] = rweights[i];
    }
}

// ---------------- GEMM1: h = silu(X@W1g) * (X@W1u) ---------------------------
// grid.x = NT_MAX row tiles, grid.y = II/TN column tiles (of intermediate dim)
__global__ __launch_bounds__(256)
void k_gemm1(const float* __restrict__ x, const float* __restrict__ w13) {
    int tile = blockIdx.x;
    if (tile >= g_num_tiles) return;
    int e     = g_tile_expert[tile];
    int row0  = g_tile_row[tile];
    int n_end = g_offsets[e + 1];
    int n0    = blockIdx.y * TN;

    __shared__ float Xs[BK][TM];
    __shared__ float Wg[BK][TN];
    __shared__ float Wu[BK][TN];

    int tid = threadIdx.x;
    int tx = tid & 15;          // 0..15 -> column group
    int ty = tid >> 4;          // 0..15 -> row group

    // X loading role: each thread loads one float4 (64 rows x 16 k / 4)
    int lrow  = tid >> 2;       // 0..63
    int lquad = tid & 3;        // 0..3
    int srow  = row0 + lrow;
    int tok   = (srow < n_end) ? g_slot_token[srow] : -1;

    // W loading role
    int wrow = tid >> 4;        // 0..15
    int wc   = (tid & 15) * 4;  // 0..60

    float accg[4][4], accu[4][4];
#pragma unroll
    for (int i = 0; i < 4; i++)
#pragma unroll
        for (int j = 0; j < 4; j++) { accg[i][j] = 0.f; accu[i][j] = 0.f; }

    const float* wbase = w13 + (size_t)e * HH * (2 * II);
    const float* xrow  = (tok >= 0) ? (x + (size_t)tok * HH) : x;

    for (int k0 = 0; k0 < HH; k0 += BK) {
        float4 xv = make_float4(0.f, 0.f, 0.f, 0.f);
        if (tok >= 0)
            xv = *reinterpret_cast<const float4*>(xrow + k0 + lquad * 4);
        Xs[lquad * 4 + 0][lrow] = xv.x;
        Xs[lquad * 4 + 1][lrow] = xv.y;
        Xs[lquad * 4 + 2][lrow] = xv.z;
        Xs[lquad * 4 + 3][lrow] = xv.w;

        const float* wp = wbase + (size_t)(k0 + wrow) * (2 * II);
        *reinterpret_cast<float4*>(&Wg[wrow][wc]) =
            *reinterpret_cast<const float4*>(wp + n0 + wc);
        *reinterpret_cast<float4*>(&Wu[wrow][wc]) =
            *reinterpret_cast<const float4*>(wp + II + n0 + wc);
        __syncthreads();

#pragma unroll
        for (int k = 0; k < BK; k++) {
            float a[4], bg[4], bu[4];
            *reinterpret_cast<float4*>(a)  = *reinterpret_cast<const float4*>(&Xs[k][ty * 4]);
            *reinterpret_cast<float4*>(bg) = *reinterpret_cast<const float4*>(&Wg[k][tx * 4]);
            *reinterpret_cast<float4*>(bu) = *reinterpret_cast<const float4*>(&Wu[k][tx * 4]);
#pragma unroll
            for (int i = 0; i < 4; i++)
#pragma unroll
                for (int j = 0; j < 4; j++) {
                    accg[i][j] += a[i] * bg[j];
                    accu[i][j] += a[i] * bu[j];
                }
        }
        __syncthreads();
    }

    // epilogue: h = silu(g) * u  -> scratch
#pragma unroll
    for (int i = 0; i < 4; i++) {
        int r = row0 + ty * 4 + i;
        if (r < n_end) {
            float4 hv;
            float* hvp = reinterpret_cast<float*>(&hv);
#pragma unroll
            for (int j = 0; j < 4; j++) {
                float g = accg[i][j];
                float s = g / (1.0f + expf(-g));
                hvp[j] = s * accu[i][j];
            }
            *reinterpret_cast<float4*>(&g_h[(size_t)r * II + n0 + tx * 4]) = hv;
        }
    }
}

// ---------------- GEMM2: out[tok] += w * (h @ W2) ----------------------------
// grid.x = NT_MAX row tiles, grid.y = HH/TN
__global__ __launch_bounds__(256)
void k_gemm2(const float* __restrict__ w2, float* __restrict__ out) {
    int tile = blockIdx.x;
    if (tile >= g_num_tiles) return;
    int e     = g_tile_expert[tile];
    int row0  = g_tile_row[tile];
    int n_end = g_offsets[e + 1];
    int n0    = blockIdx.y * TN;

    __shared__ float Hs[BK][TM];
    __shared__ float Ws[BK][TN];

    int tid = threadIdx.x;
    int tx = tid & 15;
    int ty = tid >> 4;

    int lrow  = tid >> 2;
    int lquad = tid & 3;
    int srow  = row0 + lrow;
    bool rowok = (srow < n_end);

    int wrow = tid >> 4;
    int wc   = (tid & 15) * 4;

    float acc[4][4];
#pragma unroll
    for (int i = 0; i < 4; i++)
#pragma unroll
        for (int j = 0; j < 4; j++) acc[i][j] = 0.f;

    const float* wbase = w2 + (size_t)e * II * HH;
    const float* hrow  = rowok ? (g_h + (size_t)srow * II) : g_h;

    for (int k0 = 0; k0 < II; k0 += BK) {
        float4 hv = make_float4(0.f, 0.f, 0.f, 0.f);
        if (rowok)
            hv = *reinterpret_cast<const float4*>(hrow + k0 + lquad * 4);
        Hs[lquad * 4 + 0][lrow] = hv.x;
        Hs[lquad * 4 + 1][lrow] = hv.y;
        Hs[lquad * 4 + 2][lrow] = hv.z;
        Hs[lquad * 4 + 3][lrow] = hv.w;

        *reinterpret_cast<float4*>(&Ws[wrow][wc]) =
            *reinterpret_cast<const float4*>(wbase + (size_t)(k0 + wrow) * HH + n0 + wc);
        __syncthreads();

#pragma unroll
        for (int k = 0; k < BK; k++) {
            float a[4], b[4];
            *reinterpret_cast<float4*>(a) = *reinterpret_cast<const float4*>(&Hs[k][ty * 4]);
            *reinterpret_cast<float4*>(b) = *reinterpret_cast<const float4*>(&Ws[k][tx * 4]);
#pragma unroll
            for (int i = 0; i < 4; i++)
#pragma unroll
                for (int j = 0; j < 4; j++) acc[i][j] += a[i] * b[j];
        }
        __syncthreads();
    }

#pragma unroll
    for (int i = 0; i < 4; i++) {
        int r = row0 + ty * 4 + i;
        if (r < n_end) {
            int   tok = g_slot_token[r];
            float w   = g_slot_weight[r];
            float* op = out + (size_t)tok * HH + n0 + tx * 4;
#pragma unroll
            for (int j = 0; j < 4; j++)
                atomicAdd(&op[j], w * acc[i][j]);
        }
    }
}

// ---------------- launch -----------------------------------------------------
extern "C" void kernel_launch(void* const* d_in, const int* in_sizes, int n_in,
                              void* d_out, int out_size) {
    const float* x        = (const float*)d_in[0];   // hidden_states [T,H]
    const int*   routing  = (const int*)  d_in[1];   // expert_routing_table [T,K]
    const float* rweights = (const float*)d_in[2];   // router_weights [T,K]
    const float* w13      = (const float*)d_in[3];   // [E,H,2I]
    const float* w2       = (const float*)d_in[4];   // [E,I,H]
    float*       out      = (float*)d_out;           // [T,H]

    k_init<<<1, 32>>>();
    {
        size_t n = (size_t)TT * HH;
        k_zero_out<<<(unsigned)((n + 255) / 256), 256>>>(out);
    }
    k_count<<<TKN / 256, 256>>>(routing);
    k_scan<<<1, 1>>>();
    k_scatter<<<TKN / 256, 256>>>(routing, rweights);

    dim3 g1(NT_MAX, II / TN);   // 264 x 44
    k_gemm1<<<g1, 256>>>(x, w13);

    dim3 g2(NT_MAX, HH / TN);   // 264 x 16
    k_gemm2<<<g2, 256>>>(w2, out);
}

// round 3
// speedup vs baseline: 2.1415x; 2.1415x over previous
#include <cuda_runtime.h>
#include <cuda_bf16.h>
#include <math.h>
#include <stdint.h>

// ---------------- problem constants ------------------------------------------
#define TT   8192
#define KK   2
#define HH   1024
#define II   2816
#define EE   8
#define TKN  (TT*KK)          // 16384 assignments
#define TM   128              // rows per GEMM tile
#define NT_MAX (TKN/TM + EE)  // 136 row tiles max
#define PAD  256

// GEMM tiling
#define BK    32
#define ROWB  80              // padded smem row bytes (64 data + 16 pad), 16B-aligned
#define PLANE (128*ROWB)      // 10240 B per operand plane
#define STAGE (4*PLANE)       // 40960 B per pipeline stage
#define SMEM_BYTES (2*STAGE)  // 81920 B

// ---------------- device scratch ---------------------------------------------
__device__ int   g_counts[EE];
__device__ int   g_cursor[EE];
__device__ int   g_offsets[EE + 1];
__device__ int   g_slot_token[TKN + PAD];
__device__ int   g_tok_slot[TKN];
__device__ int   g_tile_expert[NT_MAX];
__device__ int   g_tile_row[NT_MAX];
__device__ int   g_num_tiles;

__device__ __align__(256) __nv_bfloat16 g_xg_hi[(size_t)(TKN + PAD) * HH];
__device__ __align__(256) __nv_bfloat16 g_xg_lo[(size_t)(TKN + PAD) * HH];
// w13 transposed, gate/up interleaved: n=2i -> gate col i, n=2i+1 -> up col i
__device__ __align__(256) __nv_bfloat16 g_w13i_hi[(size_t)EE * 2 * II * HH];
__device__ __align__(256) __nv_bfloat16 g_w13i_lo[(size_t)EE * 2 * II * HH];
__device__ __align__(256) __nv_bfloat16 g_w2t_hi[(size_t)EE * HH * II];
__device__ __align__(256) __nv_bfloat16 g_w2t_lo[(size_t)EE * HH * II];
__device__ __align__(256) __nv_bfloat16 g_h_hi[(size_t)(TKN + PAD) * II];
__device__ __align__(256) __nv_bfloat16 g_h_lo[(size_t)(TKN + PAD) * II];
__device__ __align__(256) float         g_y[(size_t)(TKN + PAD) * HH];

// ---------------- helpers ----------------------------------------------------
__device__ __forceinline__ uint32_t smem_u32(const void* p) {
    uint32_t a;
    asm("{ .reg .u64 t; cvta.to.shared.u64 t, %1; cvt.u32.u64 %0, t; }" : "=r"(a) : "l"(p));
    return a;
}

__device__ __forceinline__ void ldmx4(uint32_t* r, uint32_t addr) {
    asm volatile("ldmatrix.sync.aligned.m8n8.x4.shared.b16 {%0,%1,%2,%3}, [%4];"
        : "=r"(r[0]), "=r"(r[1]), "=r"(r[2]), "=r"(r[3]) : "r"(addr));
}

__device__ __forceinline__ void mma16816(float* d, const uint32_t* a, const uint32_t* b) {
    asm volatile("mma.sync.aligned.m16n8k16.row.col.f32.bf16.bf16.f32 "
        "{%0,%1,%2,%3}, {%4,%5,%6,%7}, {%8,%9}, {%0,%1,%2,%3};"
        : "+f"(d[0]), "+f"(d[1]), "+f"(d[2]), "+f"(d[3])
        : "r"(a[0]), "r"(a[1]), "r"(a[2]), "r"(a[3]), "r"(b[0]), "r"(b[1]));
}

// ---------------- routing ----------------------------------------------------
__global__ void k_init() {
    int t = threadIdx.x;
    if (t < EE) { g_counts[t] = 0; g_cursor[t] = 0; }
    if (t == 0) g_num_tiles = 0;
}

__global__ void k_count(const int* __restrict__ routing) {
    int i = blockIdx.x * blockDim.x + threadIdx.x;
    if (i < TKN) atomicAdd(&g_counts[routing[i]], 1);
}

__global__ void k_scan() {
    int off = 0;
    for (int e = 0; e < EE; e++) { g_offsets[e] = off; off += g_counts[e]; }
    g_offsets[EE] = off;
    int nt = 0;
    for (int e = 0; e < EE; e++) {
        int ne = g_counts[e];
        for (int r = 0; r < ne; r += TM) {
            g_tile_expert[nt] = e;
            g_tile_row[nt]    = g_offsets[e] + r;
            nt++;
        }
    }
    g_num_tiles = nt;
}

__global__ void k_scatter(const int* __restrict__ routing) {
    int i = blockIdx.x * blockDim.x + threadIdx.x;
    if (i < TKN) {
        int e = routing[i];
        int pos = g_offsets[e] + atomicAdd(&g_cursor[e], 1);
        g_slot_token[pos] = i / KK;
        g_tok_slot[i]     = pos;
    }
}

// ---------------- conversions ------------------------------------------------
// gather X rows by slot, split fp32 -> bf16 hi/lo
__global__ __launch_bounds__(256) void k_conv_x(const float* __restrict__ x) {
    int slot = blockIdx.x;
    int tok  = g_slot_token[slot];
    int j    = threadIdx.x;                 // 256 threads x 4 floats = 1024 = HH
    float4 v = ((const float4*)(x + (size_t)tok * HH))[j];
    __nv_bfloat16 h0 = __float2bfloat16(v.x), h1 = __float2bfloat16(v.y);
    __nv_bfloat16 h2 = __float2bfloat16(v.z), h3 = __float2bfloat16(v.w);
    __nv_bfloat16 l0 = __float2bfloat16(v.x - __bfloat162float(h0));
    __nv_bfloat16 l1 = __float2bfloat16(v.y - __bfloat162float(h1));
    __nv_bfloat16 l2 = __float2bfloat16(v.z - __bfloat162float(h2));
    __nv_bfloat16 l3 = __float2bfloat16(v.w - __bfloat162float(h3));
    __nv_bfloat162* dh = (__nv_bfloat162*)(g_xg_hi + (size_t)slot * HH) + 2 * j;
    __nv_bfloat162* dl = (__nv_bfloat162*)(g_xg_lo + (size_t)slot * HH) + 2 * j;
    dh[0] = __halves2bfloat162(h0, h1); dh[1] = __halves2bfloat162(h2, h3);
    dl[0] = __halves2bfloat162(l0, l1); dl[1] = __halves2bfloat162(l2, l3);
}

// w13 [E][H][2I] -> g_w13i [E][2I][H], gate/up interleaved along n, split hi/lo
__global__ __launch_bounds__(256) void k_tconv13(const float* __restrict__ w13) {
    __shared__ float tg[32][33];
    __shared__ float tu[32][33];
    int e  = blockIdx.z;
    int i0 = blockIdx.x * 32;    // intermediate-col block
    int h0 = blockIdx.y * 32;    // hidden block
    int tx = threadIdx.x, ty = threadIdx.y;
    const float* s = w13 + (size_t)e * HH * (2 * II);
#pragma unroll
    for (int k = 0; k < 32; k += 8) {
        tg[ty + k][tx] = s[(size_t)(h0 + ty + k) * (2 * II) + i0 + tx];
        tu[ty + k][tx] = s[(size_t)(h0 + ty + k) * (2 * II) + II + i0 + tx];
    }
    __syncthreads();
    size_t db = (size_t)e * 2 * II * HH;
#pragma unroll
    for (int k = 0; k < 32; k += 8) {
        int il = ty + k;
        float vg = tg[tx][il];
        float vu = tu[tx][il];
        __nv_bfloat16 gh = __float2bfloat16(vg);
        __nv_bfloat16 uh = __float2bfloat16(vu);
        size_t og = db + (size_t)(2 * (i0 + il))     * HH + h0 + tx;
        size_t ou = db + (size_t)(2 * (i0 + il) + 1) * HH + h0 + tx;
        g_w13i_hi[og] = gh;
        g_w13i_lo[og] = __float2bfloat16(vg - __bfloat162float(gh));
        g_w13i_hi[ou] = uh;
        g_w13i_lo[ou] = __float2bfloat16(vu - __bfloat162float(uh));
    }
}

// w2 [E][I][H] -> g_w2t [E][H][I], split hi/lo
__global__ __launch_bounds__(256) void k_tconv2(const float* __restrict__ w2) {
    __shared__ float t[32][33];
    int e  = blockIdx.z;
    int c0 = blockIdx.x * 32;    // over H (cols of src)
    int r0 = blockIdx.y * 32;    // over I (rows of src)
    int tx = threadIdx.x, ty = threadIdx.y;
    const float* s = w2 + (size_t)e * II * HH;
#pragma unroll
    for (int k = 0; k < 32; k += 8)
        t[ty + k][tx] = s[(size_t)(r0 + ty + k) * HH + c0 + tx];
    __syncthreads();
    size_t db = (size_t)e * HH * II;
#pragma unroll
    for (int k = 0; k < 32; k += 8) {
        float v = t[tx][ty + k];
        __nv_bfloat16 hi = __float2bfloat16(v);
        size_t o = db + (size_t)(c0 + ty + k) * II + r0 + tx;
        g_w2t_hi[o] = hi;
        g_w2t_lo[o] = __float2bfloat16(v - __bfloat162float(hi));
    }
}

// ---------------- tensor-core grouped GEMM -----------------------------------
// MODE 1: h = silu(X@W1g)*(X@W1u)  [A=g_xg, B=g_w13i(interleaved), K=HH]
// MODE 2: y = h @ W2               [A=g_h,  B=g_w2t,               K=II]
template<int MODE>
__global__ __launch_bounds__(256, 1) void k_mma() {
    constexpr int KDIM = (MODE == 1) ? HH : II;
    constexpr int NK   = KDIM / BK;

    int tile = blockIdx.y;
    if (tile >= g_num_tiles) return;
    int e = g_tile_expert[tile], row0 = g_tile_row[tile], n_end = g_offsets[e + 1];
    int n0 = blockIdx.x * 128;
    int tid = threadIdx.x, wid = tid >> 5, lane = tid & 31;
    int wm = wid & 3, wn = wid >> 2;       // 4 x 2 warp grid
    int m0 = wm * 32, n0w = wn * 64;

    extern __shared__ char sm[];
    uint32_t sb = smem_u32(sm);

    const char *pAh, *pAl, *pBh, *pBl;
    size_t strA, strB;
    if (MODE == 1) {
        pAh = (const char*)(g_xg_hi + (size_t)row0 * HH);
        pAl = (const char*)(g_xg_lo + (size_t)row0 * HH);
        size_t wb = (size_t)e * 2 * II * HH + (size_t)n0 * HH;
        pBh = (const char*)(g_w13i_hi + wb);
        pBl = (const char*)(g_w13i_lo + wb);
        strA = HH * 2; strB = HH * 2;
    } else {
        pAh = (const char*)(g_h_hi + (size_t)row0 * II);
        pAl = (const char*)(g_h_lo + (size_t)row0 * II);
        size_t wb = (size_t)e * HH * II + (size_t)n0 * II;
        pBh = (const char*)(g_w2t_hi + wb);
        pBl = (const char*)(g_w2t_lo + wb);
        strA = II * 2; strB = II * 2;
    }
    const char* srcs[4]    = { pAh, pAl, pBh, pBl };
    size_t      strides[4] = { strA, strA, strB, strB };

    auto load_stage = [&](int ks, int s) {
        size_t ko = (size_t)ks * (BK * 2);     // bytes along K
        uint32_t dstS = sb + (uint32_t)s * STAGE;
#pragma unroll
        for (int p = 0; p < 4; p++) {
#pragma unroll
            for (int q = 0; q < 2; q++) {
                int idx = tid + q * 256;       // 512 16B-chunks per plane
                int row = idx >> 2, c16 = idx & 3;
                uint32_t d = dstS + p * PLANE + row * ROWB + c16 * 16;
                const void* g = srcs[p] + (size_t)row * strides[p] + ko + c16 * 16;
                asm volatile("cp.async.cg.shared.global [%0], [%1], 16;" :: "r"(d), "l"(g));
            }
        }
        asm volatile("cp.async.commit_group;");
    };

    float acc[16][4];
#pragma unroll
    for (int i = 0; i < 16; i++)
#pragma unroll
        for (int j = 0; j < 4; j++) acc[i][j] = 0.f;

    load_stage(0, 0);
    load_stage(1, 1);

    for (int ks = 0; ks < NK; ks++) {
        int s = ks & 1;
        if (ks + 1 < NK) asm volatile("cp.async.wait_group 1;");
        else             asm volatile("cp.async.wait_group 0;");
        __syncthreads();
        uint32_t base = sb + (uint32_t)s * STAGE;
#pragma unroll
        for (int sub = 0; sub < 2; sub++) {
            uint32_t aoff = (uint32_t)((lane & 15) * ROWB + ((lane >> 4) << 4) + sub * 32);
            uint32_t ah[2][4], al[2][4];
            ldmx4(ah[0], base + 0 * PLANE + (m0 + 0)  * ROWB + aoff);
            ldmx4(ah[1], base + 0 * PLANE + (m0 + 16) * ROWB + aoff);
            ldmx4(al[0], base + 1 * PLANE + (m0 + 0)  * ROWB + aoff);
            ldmx4(al[1], base + 1 * PLANE + (m0 + 16) * ROWB + aoff);
            uint32_t boff = (uint32_t)(((lane & 7) + ((lane >> 4) << 3)) * ROWB
                                       + ((lane >> 3) & 1) * 16 + sub * 32);
#pragma unroll
            for (int jj = 0; jj < 4; jj++) {
                uint32_t bh[4], bl[4];
                ldmx4(bh, base + 2 * PLANE + (n0w + jj * 16) * ROWB + boff);
                ldmx4(bl, base + 3 * PLANE + (n0w + jj * 16) * ROWB + boff);
                // term-major ordering: each acc revisited every 4 MMAs
#pragma unroll
                for (int i = 0; i < 2; i++) {
                    mma16816(acc[i * 8 + jj * 2 + 0], ah[i], bh + 0);
                    mma16816(acc[i * 8 + jj * 2 + 1], ah[i], bh + 2);
                }
#pragma unroll
                for (int i = 0; i < 2; i++) {
                    mma16816(acc[i * 8 + jj * 2 + 0], ah[i], bl + 0);
                    mma16816(acc[i * 8 + jj * 2 + 1], ah[i], bl + 2);
                }
#pragma unroll
                for (int i = 0; i < 2; i++) {
                    mma16816(acc[i * 8 + jj * 2 + 0], al[i], bh + 0);
                    mma16816(acc[i * 8 + jj * 2 + 1], al[i], bh + 2);
                }
            }
        }
        __syncthreads();
        if (ks + 2 < NK) load_stage(ks + 2, s);
    }

    // ---------------- epilogue ----------------
    int rbase = row0 + m0 + (lane >> 2);
    int q     = lane & 3;
#pragma unroll
    for (int i = 0; i < 2; i++) {
        int ra = rbase + i * 16;
#pragma unroll
        for (int j = 0; j < 8; j++) {
            const float* c = acc[i * 8 + j];
            if (MODE == 1) {
                int hcol = ((n0 + n0w + j * 8) >> 1) + q;
                if (ra < n_end) {
                    float g = c[0], u = c[1];
                    float h = u * (g / (1.0f + __expf(-g)));
                    __nv_bfloat16 hh = __float2bfloat16(h);
                    g_h_hi[(size_t)ra * II + hcol] = hh;
                    g_h_lo[(size_t)ra * II + hcol] = __float2bfloat16(h - __bfloat162float(hh));
                }
                if (ra + 8 < n_end) {
                    float g = c[2], u = c[3];
                    float h = u * (g / (1.0f + __expf(-g)));
                    __nv_bfloat16 hh = __float2bfloat16(h);
                    g_h_hi[(size_t)(ra + 8) * II + hcol] = hh;
                    g_h_lo[(size_t)(ra + 8) * II + hcol] = __float2bfloat16(h - __bfloat162float(hh));
                }
            } else {
                int col = n0 + n0w + j * 8 + 2 * q;
                if (ra < n_end) {
                    float2 v = make_float2(c[0], c[1]);
                    *(float2*)(g_y + (size_t)ra * HH + col) = v;
                }
                if (ra + 8 < n_end) {
                    float2 v = make_float2(c[2], c[3]);
                    *(float2*)(g_y + (size_t)(ra + 8) * HH + col) = v;
                }
            }
        }
    }
}

// ---------------- combine: out[t] = sum_k rw[t,k] * y[slot(t,k)] -------------
__global__ __launch_bounds__(256) void k_combine(const float* __restrict__ rw,
                                                 float* __restrict__ out) {
    size_t i = (size_t)blockIdx.x * blockDim.x + threadIdx.x;
    if (i >= (size_t)TT * HH) return;
    int t = (int)(i >> 10);
    int h = (int)(i & 1023);
    int s0 = g_tok_slot[2 * t], s1 = g_tok_slot[2 * t + 1];
    out[i] = rw[2 * t] * g_y[(size_t)s0 * HH + h] + rw[2 * t + 1] * g_y[(size_t)s1 * HH + h];
}

// ---------------- launch -----------------------------------------------------
extern "C" void kernel_launch(void* const* d_in, const int* in_sizes, int n_in,
                              void* d_out, int out_size) {
    const float* x        = (const float*)d_in[0];   // [T,H]
    const int*   routing  = (const int*)  d_in[1];   // [T,K]
    const float* rweights = (const float*)d_in[2];   // [T,K]
    const float* w13      = (const float*)d_in[3];   // [E,H,2I]
    const float* w2       = (const float*)d_in[4];   // [E,I,H]
    float*       out      = (float*)d_out;           // [T,H]

    cudaFuncSetAttribute(k_mma<1>, cudaFuncAttributeMaxDynamicSharedMemorySize, SMEM_BYTES);
    cudaFuncSetAttribute(k_mma<2>, cudaFuncAttributeMaxDynamicSharedMemorySize, SMEM_BYTES);

    // routing
    k_init<<<1, 32>>>();
    k_count<<<TKN / 256, 256>>>(routing);
    k_scan<<<1, 1>>>();
    k_scatter<<<TKN / 256, 256>>>(routing);

    // conversions
    k_conv_x<<<TKN, 256>>>(x);
    {
        dim3 g(II / 32, HH / 32, EE);    // 88 x 32 x 8
        k_tconv13<<<g, dim3(32, 8)>>>(w13);
    }
    {
        dim3 g(HH / 32, II / 32, EE);    // 32 x 88 x 8
        k_tconv2<<<g, dim3(32, 8)>>>(w2);
    }

    // GEMMs
    k_mma<1><<<dim3(2 * II / 128, NT_MAX), 256, SMEM_BYTES>>>();   // 44 x 136
    k_mma<2><<<dim3(HH / 128, NT_MAX), 256, SMEM_BYTES>>>();       // 8 x 136

    // combine
    {
        size_t n = (size_t)TT * HH;
        k_combine<<<(unsigned)((n + 255) / 256), 256>>>(rweights, out);
    }
}

// round 4
// speedup vs baseline: 2.8832x; 1.3463x over previous
#include <cuda_runtime.h>
#include <cuda_bf16.h>
#include <math.h>
#include <stdint.h>

// ---------------- problem constants ------------------------------------------
#define TT   8192
#define KK   2
#define HH   1024
#define II   2816
#define EE   8
#define TKN  (TT*KK)          // 16384 assignments
#define TM   128              // rows per GEMM tile
#define NT_MAX (TKN/TM + EE)  // 136 row tiles max
#define PAD  256

// GEMM tiling
#define BK    32
#define ROWB  80              // padded smem row bytes (64 data + 16 pad), 16B-aligned
#define PLANE (128*ROWB)      // 10240 B per operand plane
#define STAGE (4*PLANE)       // 40960 B per pipeline stage
#define SMEM_BYTES (2*STAGE)  // 81920 B

// ---------------- device scratch ---------------------------------------------
__device__ int   g_offsets[EE + 1];
__device__ int   g_slot_token[TKN + PAD];
__device__ int   g_tok_slot[TKN];
__device__ int   g_tile_expert[NT_MAX];
__device__ int   g_tile_row[NT_MAX];
__device__ int   g_num_tiles;

__device__ __align__(256) __nv_bfloat16 g_xg_hi[(size_t)(TKN + PAD) * HH];
__device__ __align__(256) __nv_bfloat16 g_xg_lo[(size_t)(TKN + PAD) * HH];
// w13 transposed, gate/up interleaved: n=2i -> gate col i, n=2i+1 -> up col i
__device__ __align__(256) __nv_bfloat16 g_w13i_hi[(size_t)EE * 2 * II * HH];
__device__ __align__(256) __nv_bfloat16 g_w13i_lo[(size_t)EE * 2 * II * HH];
__device__ __align__(256) __nv_bfloat16 g_w2t_hi[(size_t)EE * HH * II];
__device__ __align__(256) __nv_bfloat16 g_w2t_lo[(size_t)EE * HH * II];
__device__ __align__(256) __nv_bfloat16 g_h_hi[(size_t)(TKN + PAD) * II];
__device__ __align__(256) __nv_bfloat16 g_h_lo[(size_t)(TKN + PAD) * II];
__device__ __align__(256) float         g_y[(size_t)(TKN + PAD) * HH];

// ---------------- helpers ----------------------------------------------------
__device__ __forceinline__ uint32_t smem_u32(const void* p) {
    uint32_t a;
    asm("{ .reg .u64 t; cvta.to.shared.u64 t, %1; cvt.u32.u64 %0, t; }" : "=r"(a) : "l"(p));
    return a;
}

__device__ __forceinline__ void ldmx4(uint32_t* r, uint32_t addr) {
    asm volatile("ldmatrix.sync.aligned.m8n8.x4.shared.b16 {%0,%1,%2,%3}, [%4];"
        : "=r"(r[0]), "=r"(r[1]), "=r"(r[2]), "=r"(r[3]) : "r"(addr));
}

__device__ __forceinline__ void mma16816(float* d, const uint32_t* a, const uint32_t* b) {
    asm volatile("mma.sync.aligned.m16n8k16.row.col.f32.bf16.bf16.f32 "
        "{%0,%1,%2,%3}, {%4,%5,%6,%7}, {%8,%9}, {%0,%1,%2,%3};"
        : "+f"(d[0]), "+f"(d[1]), "+f"(d[2]), "+f"(d[3])
        : "r"(a[0]), "r"(a[1]), "r"(a[2]), "r"(a[3]), "r"(b[0]), "r"(b[1]));
}

__device__ __forceinline__ uint32_t pack_h(float g, float u) {
    float h = u * (g / (1.0f + __expf(-g)));
    __nv_bfloat16 hh = __float2bfloat16(h);
    __nv_bfloat16 hl = __float2bfloat16(h - __bfloat162float(hh));
    return (uint32_t)__bfloat16_as_ushort(hh) | ((uint32_t)__bfloat16_as_ushort(hl) << 16);
}

// ---------------- fused routing (single CTA) ---------------------------------
__global__ __launch_bounds__(1024) void k_route(const int* __restrict__ routing) {
    __shared__ int sc[EE];
    __shared__ int so[EE];
    __shared__ int scur[EE];
    int tid = threadIdx.x;
    if (tid < EE) { sc[tid] = 0; scur[tid] = 0; }
    __syncthreads();
    for (int i = tid; i < TKN; i += 1024) atomicAdd(&sc[routing[i]], 1);
    __syncthreads();
    if (tid == 0) {
        int off = 0, nt = 0;
        for (int e = 0; e < EE; e++) {
            so[e] = off; g_offsets[e] = off;
            for (int r = 0; r < sc[e]; r += TM) {
                g_tile_expert[nt] = e;
                g_tile_row[nt]    = off + r;
                nt++;
            }
            off += sc[e];
        }
        g_offsets[EE] = off;
        g_num_tiles = nt;
    }
    __syncthreads();
    for (int i = tid; i < TKN; i += 1024) {
        int e = routing[i];
        int pos = so[e] + atomicAdd(&scur[e], 1);
        g_slot_token[pos] = i >> 1;           // KK=2
        g_tok_slot[i]     = pos;
    }
}

// ---------------- conversions ------------------------------------------------
__global__ __launch_bounds__(256) void k_conv_x(const float* __restrict__ x) {
    int slot = blockIdx.x;
    int tok  = g_slot_token[slot];
    int j    = threadIdx.x;                 // 256 threads x 4 floats = 1024 = HH
    float4 v = ((const float4*)(x + (size_t)tok * HH))[j];
    __nv_bfloat16 h0 = __float2bfloat16(v.x), h1 = __float2bfloat16(v.y);
    __nv_bfloat16 h2 = __float2bfloat16(v.z), h3 = __float2bfloat16(v.w);
    __nv_bfloat16 l0 = __float2bfloat16(v.x - __bfloat162float(h0));
    __nv_bfloat16 l1 = __float2bfloat16(v.y - __bfloat162float(h1));
    __nv_bfloat16 l2 = __float2bfloat16(v.z - __bfloat162float(h2));
    __nv_bfloat16 l3 = __float2bfloat16(v.w - __bfloat162float(h3));
    __nv_bfloat162* dh = (__nv_bfloat162*)(g_xg_hi + (size_t)slot * HH) + 2 * j;
    __nv_bfloat162* dl = (__nv_bfloat162*)(g_xg_lo + (size_t)slot * HH) + 2 * j;
    dh[0] = __halves2bfloat162(h0, h1); dh[1] = __halves2bfloat162(h2, h3);
    dl[0] = __halves2bfloat162(l0, l1); dl[1] = __halves2bfloat162(l2, l3);
}

// w13 [E][H][2I] -> g_w13i [E][2I][H], gate/up interleaved along n, split hi/lo
__global__ __launch_bounds__(256) void k_tconv13(const float* __restrict__ w13) {
    __shared__ float tg[32][33];
    __shared__ float tu[32][33];
    int e  = blockIdx.z;
    int i0 = blockIdx.x * 32;
    int h0 = blockIdx.y * 32;
    int tx = threadIdx.x, ty = threadIdx.y;
    const float* s = w13 + (size_t)e * HH * (2 * II);
#pragma unroll
    for (int k = 0; k < 32; k += 8) {
        tg[ty + k][tx] = s[(size_t)(h0 + ty + k) * (2 * II) + i0 + tx];
        tu[ty + k][tx] = s[(size_t)(h0 + ty + k) * (2 * II) + II + i0 + tx];
    }
    __syncthreads();
    size_t db = (size_t)e * 2 * II * HH;
#pragma unroll
    for (int k = 0; k < 32; k += 8) {
        int il = ty + k;
        float vg = tg[tx][il];
        float vu = tu[tx][il];
        __nv_bfloat16 gh = __float2bfloat16(vg);
        __nv_bfloat16 uh = __float2bfloat16(vu);
        size_t og = db + (size_t)(2 * (i0 + il))     * HH + h0 + tx;
        size_t ou = db + (size_t)(2 * (i0 + il) + 1) * HH + h0 + tx;
        g_w13i_hi[og] = gh;
        g_w13i_lo[og] = __float2bfloat16(vg - __bfloat162float(gh));
        g_w13i_hi[ou] = uh;
        g_w13i_lo[ou] = __float2bfloat16(vu - __bfloat162float(uh));
    }
}

// w2 [E][I][H] -> g_w2t [E][H][I], split hi/lo
__global__ __launch_bounds__(256) void k_tconv2(const float* __restrict__ w2) {
    __shared__ float t[32][33];
    int e  = blockIdx.z;
    int c0 = blockIdx.x * 32;
    int r0 = blockIdx.y * 32;
    int tx = threadIdx.x, ty = threadIdx.y;
    const float* s = w2 + (size_t)e * II * HH;
#pragma unroll
    for (int k = 0; k < 32; k += 8)
        t[ty + k][tx] = s[(size_t)(r0 + ty + k) * HH + c0 + tx];
    __syncthreads();
    size_t db = (size_t)e * HH * II;
#pragma unroll
    for (int k = 0; k < 32; k += 8) {
        float v = t[tx][ty + k];
        __nv_bfloat16 hi = __float2bfloat16(v);
        size_t o = db + (size_t)(c0 + ty + k) * II + r0 + tx;
        g_w2t_hi[o] = hi;
        g_w2t_lo[o] = __float2bfloat16(v - __bfloat162float(hi));
    }
}

// ---------------- tensor-core grouped GEMM -----------------------------------
// MODE 1: h = silu(X@W1g)*(X@W1u)  [A=g_xg, B=g_w13i(interleaved), K=HH]
// MODE 2: y = h @ W2               [A=g_h,  B=g_w2t,               K=II]
template<int MODE>
__global__ __launch_bounds__(256, 2) void k_mma() {
    constexpr int KDIM = (MODE == 1) ? HH : II;
    constexpr int NK   = KDIM / BK;
    constexpr size_t STRD = (MODE == 1) ? (size_t)HH * 2 : (size_t)II * 2;

    int tile = blockIdx.y;
    if (tile >= g_num_tiles) return;
    int e = g_tile_expert[tile], row0 = g_tile_row[tile], n_end = g_offsets[e + 1];
    int n0 = blockIdx.x * 128;
    int tid = threadIdx.x, wid = tid >> 5, lane = tid & 31;
    int wm = wid & 3, wn = wid >> 2;       // 4 x 2 warp grid
    int m0 = wm * 32, n0w = wn * 64;

    extern __shared__ char sm[];
    uint32_t sb = smem_u32(sm);

    const char *pAh, *pAl, *pBh, *pBl;
    if (MODE == 1) {
        pAh = (const char*)(g_xg_hi + (size_t)row0 * HH);
        pAl = (const char*)(g_xg_lo + (size_t)row0 * HH);
        size_t wb = (size_t)e * 2 * II * HH + (size_t)n0 * HH;
        pBh = (const char*)(g_w13i_hi + wb);
        pBl = (const char*)(g_w13i_lo + wb);
    } else {
        pAh = (const char*)(g_h_hi + (size_t)row0 * II);
        pAl = (const char*)(g_h_lo + (size_t)row0 * II);
        size_t wb = (size_t)e * HH * II + (size_t)n0 * II;
        pBh = (const char*)(g_w2t_hi + wb);
        pBl = (const char*)(g_w2t_lo + wb);
    }

    // per-thread auto-advancing load pointers (8): 4 planes x 2 row-groups
    int lrow = tid >> 2, lc16 = tid & 3;
    size_t tho = (size_t)lrow * STRD + (size_t)lc16 * 16;
    const char* gp[8];
    gp[0] = pAh + tho; gp[1] = gp[0] + 64 * STRD;
    gp[2] = pAl + tho; gp[3] = gp[2] + 64 * STRD;
    gp[4] = pBh + tho; gp[5] = gp[4] + 64 * STRD;
    gp[6] = pBl + tho; gp[7] = gp[6] + 64 * STRD;
    uint32_t dof = (uint32_t)lrow * ROWB + (uint32_t)lc16 * 16;

    auto load_stage = [&](int s) {
        uint32_t dstS = sb + (uint32_t)s * STAGE + dof;
#pragma unroll
        for (int p = 0; p < 4; p++) {
            uint32_t d0 = dstS + p * PLANE;
            asm volatile("cp.async.cg.shared.global [%0], [%1], 16;" :: "r"(d0), "l"(gp[2 * p]));
            asm volatile("cp.async.cg.shared.global [%0], [%1], 16;" :: "r"(d0 + 64 * ROWB), "l"(gp[2 * p + 1]));
            gp[2 * p]     += 64;
            gp[2 * p + 1] += 64;
        }
        asm volatile("cp.async.commit_group;");
    };

    float acc[16][4];
#pragma unroll
    for (int i = 0; i < 16; i++)
#pragma unroll
        for (int j = 0; j < 4; j++) acc[i][j] = 0.f;

    load_stage(0);
    load_stage(1);

    for (int ks = 0; ks < NK; ks++) {
        int s = ks & 1;
        if (ks + 1 < NK) asm volatile("cp.async.wait_group 1;");
        else             asm volatile("cp.async.wait_group 0;");
        __syncthreads();
        uint32_t base = sb + (uint32_t)s * STAGE;
#pragma unroll
        for (int sub = 0; sub < 2; sub++) {
            uint32_t aoff = (uint32_t)((lane & 15) * ROWB + ((lane >> 4) << 4) + sub * 32);
            uint32_t ah[2][4], al[2][4];
            ldmx4(ah[0], base + 0 * PLANE + (m0 + 0)  * ROWB + aoff);
            ldmx4(ah[1], base + 0 * PLANE + (m0 + 16) * ROWB + aoff);
            ldmx4(al[0], base + 1 * PLANE + (m0 + 0)  * ROWB + aoff);
            ldmx4(al[1], base + 1 * PLANE + (m0 + 16) * ROWB + aoff);
            uint32_t boff = (uint32_t)(((lane & 7) + ((lane >> 4) << 3)) * ROWB
                                       + ((lane >> 3) & 1) * 16 + sub * 32);
#pragma unroll
            for (int jj = 0; jj < 4; jj++) {
                uint32_t bh[4], bl[4];
                ldmx4(bh, base + 2 * PLANE + (n0w + jj * 16) * ROWB + boff);
                ldmx4(bl, base + 3 * PLANE + (n0w + jj * 16) * ROWB + boff);
#pragma unroll
                for (int i = 0; i < 2; i++) {
                    mma16816(acc[i * 8 + jj * 2 + 0], ah[i], bh + 0);
                    mma16816(acc[i * 8 + jj * 2 + 1], ah[i], bh + 2);
                }
#pragma unroll
                for (int i = 0; i < 2; i++) {
                    mma16816(acc[i * 8 + jj * 2 + 0], ah[i], bl + 0);
                    mma16816(acc[i * 8 + jj * 2 + 1], ah[i], bl + 2);
                }
#pragma unroll
                for (int i = 0; i < 2; i++) {
                    mma16816(acc[i * 8 + jj * 2 + 0], al[i], bh + 0);
                    mma16816(acc[i * 8 + jj * 2 + 1], al[i], bh + 2);
                }
            }
        }
        __syncthreads();
        if (ks + 2 < NK) load_stage(s);
    }

    // ---------------- epilogue ----------------
    if (MODE == 1) {
        // stage packed (hi,lo) h values in smem (68-word padded rows), then
        // write out coalesced.
        __syncthreads();
        uint32_t* st = (uint32_t*)sm;
        int q = lane & 3;
        int rl = m0 + (lane >> 2);
#pragma unroll
        for (int i = 0; i < 2; i++) {
#pragma unroll
            for (int j = 0; j < 8; j++) {
                const float* c = acc[i * 8 + j];
                int hcl = ((n0w + j * 8) >> 1) + q;
                st[(rl + i * 16)     * 68 + hcl] = pack_h(c[0], c[1]);
                st[(rl + i * 16 + 8) * 68 + hcl] = pack_h(c[2], c[3]);
            }
        }
        __syncthreads();
        int hb = n0 >> 1;
#pragma unroll
        for (int pass = 0; pass < 8; pass++) {
            int r  = pass * 16 + (tid >> 4);
            int c4 = (tid & 15) * 4;
            int grow = row0 + r;
            if (grow < n_end) {
                uint32_t w0 = st[r * 68 + c4 + 0], w1 = st[r * 68 + c4 + 1];
                uint32_t w2 = st[r * 68 + c4 + 2], w3 = st[r * 68 + c4 + 3];
                uint32_t hi0 = (w0 & 0xffffu) | (w1 << 16);
                uint32_t hi1 = (w2 & 0xffffu) | (w3 << 16);
                uint32_t lo0 = (w0 >> 16) | (w1 & 0xffff0000u);
                uint32_t lo1 = (w2 >> 16) | (w3 & 0xffff0000u);
                size_t off = (size_t)grow * II + hb + c4;
                *(uint2*)(g_h_hi + off) = make_uint2(hi0, hi1);
                *(uint2*)(g_h_lo + off) = make_uint2(lo0, lo1);
            }
        }
    } else {
        int rbase = row0 + m0 + (lane >> 2);
        int q     = lane & 3;
#pragma unroll
        for (int i = 0; i < 2; i++) {
            int ra = rbase + i * 16;
#pragma unroll
            for (int j = 0; j < 8; j++) {
                const float* c = acc[i * 8 + j];
                int col = n0 + n0w + j * 8 + 2 * q;
                if (ra < n_end)
                    *(float2*)(g_y + (size_t)ra * HH + col) = make_float2(c[0], c[1]);
                if (ra + 8 < n_end)
                    *(float2*)(g_y + (size_t)(ra + 8) * HH + col) = make_float2(c[2], c[3]);
            }
        }
    }
}

// ---------------- combine: out[t] = sum_k rw[t,k] * y[slot(t,k)] -------------
__global__ __launch_bounds__(256) void k_combine(const float* __restrict__ rw,
                                                 float* __restrict__ out) {
    size_t i = (size_t)blockIdx.x * blockDim.x + threadIdx.x;
    if (i >= (size_t)TT * HH) return;
    int t = (int)(i >> 10);
    int h = (int)(i & 1023);
    int s0 = g_tok_slot[2 * t], s1 = g_tok_slot[2 * t + 1];
    out[i] = rw[2 * t] * g_y[(size_t)s0 * HH + h] + rw[2 * t + 1] * g_y[(size_t)s1 * HH + h];
}

// ---------------- launch -----------------------------------------------------
extern "C" void kernel_launch(void* const* d_in, const int* in_sizes, int n_in,
                              void* d_out, int out_size) {
    const float* x        = (const float*)d_in[0];   // [T,H]
    const int*   routing  = (const int*)  d_in[1];   // [T,K]
    const float* rweights = (const float*)d_in[2];   // [T,K]
    const float* w13      = (const float*)d_in[3];   // [E,H,2I]
    const float* w2       = (const float*)d_in[4];   // [E,I,H]
    float*       out      = (float*)d_out;           // [T,H]

    cudaFuncSetAttribute(k_mma<1>, cudaFuncAttributeMaxDynamicSharedMemorySize, SMEM_BYTES);
    cudaFuncSetAttribute(k_mma<2>, cudaFuncAttributeMaxDynamicSharedMemorySize, SMEM_BYTES);

    // weight conversions first (independent of routing) — pushes the GEMMs
    // into the ncu capture window
    {
        dim3 g(II / 32, HH / 32, EE);    // 88 x 32 x 8
        k_tconv13<<<g, dim3(32, 8)>>>(w13);
    }
    {
        dim3 g(HH / 32, II / 32, EE);    // 32 x 88 x 8
        k_tconv2<<<g, dim3(32, 8)>>>(w2);
    }

    // routing (fused) + X gather/split
    k_route<<<1, 1024>>>(routing);
    k_conv_x<<<TKN, 256>>>(x);

    // GEMMs
    k_mma<1><<<dim3(2 * II / 128, NT_MAX), 256, SMEM_BYTES>>>();   // 44 x 136
    k_mma<2><<<dim3(HH / 128, NT_MAX), 256, SMEM_BYTES>>>();       // 8 x 136

    // combine
    {
        size_t n = (size_t)TT * HH;
        k_combine<<<(unsigned)((n + 255) / 256), 256>>>(rweights, out);
    }
}

// round 6
// speedup vs baseline: 3.4156x; 1.1847x over previous
#include <cuda_runtime.h>
#include <cuda_bf16.h>
#include <math.h>
#include <stdint.h>

// ---------------- problem constants ------------------------------------------
#define TT   8192
#define KK   2
#define HH   1024
#define II   2816
#define EE   8
#define TKN  (TT*KK)          // 16384 assignments
#define TM   128              // rows per GEMM tile
#define NT_MAX (TKN/TM + EE)  // 136 row tiles max
#define PAD  256

// GEMM tiling: swizzled smem, no padding
#define BK    32
#define PLANE (128*64)        // 8192 B per operand plane (128 rows x 64 B)
#define STAGE (4*PLANE)       // 32768 B per pipeline stage
#define NSTG  3
#define SMEM_BYTES (NSTG*STAGE)  // 98304 B

// ---------------- device scratch ---------------------------------------------
__device__ int   g_offsets[EE + 1];
__device__ int   g_slot_token[TKN + PAD];
__device__ int   g_tok_slot[TKN];
__device__ int   g_tile_expert[NT_MAX];
__device__ int   g_tile_row[NT_MAX];
__device__ int   g_num_tiles;

__device__ __align__(256) __nv_bfloat16 g_xg_hi[(size_t)(TKN + PAD) * HH];
__device__ __align__(256) __nv_bfloat16 g_xg_lo[(size_t)(TKN + PAD) * HH];
// w13 transposed, gate/up interleaved: n=2i -> gate col i, n=2i+1 -> up col i
__device__ __align__(256) __nv_bfloat16 g_w13i_hi[(size_t)EE * 2 * II * HH];
__device__ __align__(256) __nv_bfloat16 g_w13i_lo[(size_t)EE * 2 * II * HH];
__device__ __align__(256) __nv_bfloat16 g_w2t_hi[(size_t)EE * HH * II];
__device__ __align__(256) __nv_bfloat16 g_w2t_lo[(size_t)EE * HH * II];
__device__ __align__(256) __nv_bfloat16 g_h_hi[(size_t)(TKN + PAD) * II];
__device__ __align__(256) __nv_bfloat16 g_h_lo[(size_t)(TKN + PAD) * II];
__device__ __align__(256) float         g_y[(size_t)(TKN + PAD) * HH];

// ---------------- helpers ----------------------------------------------------
__device__ __forceinline__ uint32_t smem_u32(const void* p) {
    uint32_t a;
    asm("{ .reg .u64 t; cvta.to.shared.u64 t, %1; cvt.u32.u64 %0, t; }" : "=r"(a) : "l"(p));
    return a;
}

__device__ __forceinline__ void ldmx4(uint32_t* r, uint32_t addr) {
    asm volatile("ldmatrix.sync.aligned.m8n8.x4.shared.b16 {%0,%1,%2,%3}, [%4];"
        : "=r"(r[0]), "=r"(r[1]), "=r"(r[2]), "=r"(r[3]) : "r"(addr));
}

__device__ __forceinline__ void mma16816(float* d, const uint32_t* a, const uint32_t* b) {
    asm volatile("mma.sync.aligned.m16n8k16.row.col.f32.bf16.bf16.f32 "
        "{%0,%1,%2,%3}, {%4,%5,%6,%7}, {%8,%9}, {%0,%1,%2,%3};"
        : "+f"(d[0]), "+f"(d[1]), "+f"(d[2]), "+f"(d[3])
        : "r"(a[0]), "r"(a[1]), "r"(a[2]), "r"(a[3]), "r"(b[0]), "r"(b[1]));
}

__device__ __forceinline__ uint32_t pack_h(float g, float u) {
    float h = u * (g / (1.0f + __expf(-g)));
    __nv_bfloat16 hh = __float2bfloat16(h);
    __nv_bfloat16 hl = __float2bfloat16(h - __bfloat162float(hh));
    return (uint32_t)__bfloat16_as_ushort(hh) | ((uint32_t)__bfloat16_as_ushort(hl) << 16);
}

// ---------------- fused routing (single CTA) ---------------------------------
__global__ __launch_bounds__(1024) void k_route(const int* __restrict__ routing) {
    __shared__ int sc[EE];
    __shared__ int so[EE];
    __shared__ int scur[EE];
    int tid = threadIdx.x;
    if (tid < EE) { sc[tid] = 0; scur[tid] = 0; }
    __syncthreads();
    for (int i = tid; i < TKN; i += 1024) atomicAdd(&sc[routing[i]], 1);
    __syncthreads();
    if (tid == 0) {
        int off = 0, nt = 0;
        for (int e = 0; e < EE; e++) {
            so[e] = off; g_offsets[e] = off;
            for (int r = 0; r < sc[e]; r += TM) {
                g_tile_expert[nt] = e;
                g_tile_row[nt]    = off + r;
                nt++;
            }
            off += sc[e];
        }
        g_offsets[EE] = off;
        g_num_tiles = nt;
    }
    __syncthreads();
    for (int i = tid; i < TKN; i += 1024) {
        int e = routing[i];
        int pos = so[e] + atomicAdd(&scur[e], 1);
        g_slot_token[pos] = i >> 1;           // KK=2
        g_tok_slot[i]     = pos;
    }
}

// ---------------- conversions ------------------------------------------------
__global__ __launch_bounds__(256) void k_conv_x(const float* __restrict__ x) {
    int slot = blockIdx.x;
    int tok  = g_slot_token[slot];
    int j    = threadIdx.x;                 // 256 threads x 4 floats = 1024 = HH
    float4 v = ((const float4*)(x + (size_t)tok * HH))[j];
    __nv_bfloat16 h0 = __float2bfloat16(v.x), h1 = __float2bfloat16(v.y);
    __nv_bfloat16 h2 = __float2bfloat16(v.z), h3 = __float2bfloat16(v.w);
    __nv_bfloat16 l0 = __float2bfloat16(v.x - __bfloat162float(h0));
    __nv_bfloat16 l1 = __float2bfloat16(v.y - __bfloat162float(h1));
    __nv_bfloat16 l2 = __float2bfloat16(v.z - __bfloat162float(h2));
    __nv_bfloat16 l3 = __float2bfloat16(v.w - __bfloat162float(h3));
    __nv_bfloat162* dh = (__nv_bfloat162*)(g_xg_hi + (size_t)slot * HH) + 2 * j;
    __nv_bfloat162* dl = (__nv_bfloat162*)(g_xg_lo + (size_t)slot * HH) + 2 * j;
    dh[0] = __halves2bfloat162(h0, h1); dh[1] = __halves2bfloat162(h2, h3);
    dl[0] = __halves2bfloat162(l0, l1); dl[1] = __halves2bfloat162(l2, l3);
}

// w13 [E][H][2I] -> g_w13i [E][2I][H], gate/up interleaved along n, split hi/lo
__global__ __launch_bounds__(256) void k_tconv13(const float* __restrict__ w13) {
    __shared__ float tg[32][33];
    __shared__ float tu[32][33];
    int e  = blockIdx.z;
    int i0 = blockIdx.x * 32;
    int h0 = blockIdx.y * 32;
    int tx = threadIdx.x, ty = threadIdx.y;
    const float* s = w13 + (size_t)e * HH * (2 * II);
#pragma unroll
    for (int k = 0; k < 32; k += 8) {
        tg[ty + k][tx] = s[(size_t)(h0 + ty + k) * (2 * II) + i0 + tx];
        tu[ty + k][tx] = s[(size_t)(h0 + ty + k) * (2 * II) + II + i0 + tx];
    }
    __syncthreads();
    size_t db = (size_t)e * 2 * II * HH;
#pragma unroll
    for (int k = 0; k < 32; k += 8) {
        int il = ty + k;
        float vg = tg[tx][il];
        float vu = tu[tx][il];
        __nv_bfloat16 gh = __float2bfloat16(vg);
        __nv_bfloat16 uh = __float2bfloat16(vu);
        size_t og = db + (size_t)(2 * (i0 + il))     * HH + h0 + tx;
        size_t ou = db + (size_t)(2 * (i0 + il) + 1) * HH + h0 + tx;
        g_w13i_hi[og] = gh;
        g_w13i_lo[og] = __float2bfloat16(vg - __bfloat162float(gh));
        g_w13i_hi[ou] = uh;
        g_w13i_lo[ou] = __float2bfloat16(vu - __bfloat162float(uh));
    }
}

// w2 [E][I][H] -> g_w2t [E][H][I], split hi/lo
__global__ __launch_bounds__(256) void k_tconv2(const float* __restrict__ w2) {
    __shared__ float t[32][33];
    int e  = blockIdx.z;
    int c0 = blockIdx.x * 32;
    int r0 = blockIdx.y * 32;
    int tx = threadIdx.x, ty = threadIdx.y;
    const float* s = w2 + (size_t)e * II * HH;
#pragma unroll
    for (int k = 0; k < 32; k += 8)
        t[ty + k][tx] = s[(size_t)(r0 + ty + k) * HH + c0 + tx];
    __syncthreads();
    size_t db = (size_t)e * HH * II;
#pragma unroll
    for (int k = 0; k < 32; k += 8) {
        float v = t[tx][ty + k];
        __nv_bfloat16 hi = __float2bfloat16(v);
        size_t o = db + (size_t)(c0 + ty + k) * II + r0 + tx;
        g_w2t_hi[o] = hi;
        g_w2t_lo[o] = __float2bfloat16(v - __bfloat162float(hi));
    }
}

// ---------------- tensor-core grouped GEMM -----------------------------------
// smem layout per stage: 4 planes (Ah, Al, Bh, Bl), each 128 rows x 64 B,
// chunk-swizzled: addr(row, chunk) = row*64 + (chunk ^ ((row>>1)&3))*16
// MODE 1: h = silu(X@W1g)*(X@W1u)  [A=g_xg, B=g_w13i(interleaved), K=HH]
// MODE 2: y = h @ W2               [A=g_h,  B=g_w2t,               K=II]
template<int MODE>
__global__ __launch_bounds__(256, 2) void k_mma() {
    constexpr int KDIM = (MODE == 1) ? HH : II;
    constexpr int NK   = KDIM / BK;
    constexpr size_t STRD = (MODE == 1) ? (size_t)HH * 2 : (size_t)II * 2;

    int tile = blockIdx.y;
    if (tile >= g_num_tiles) return;
    int e = g_tile_expert[tile], row0 = g_tile_row[tile], n_end = g_offsets[e + 1];
    int n0 = blockIdx.x * 128;
    int tid = threadIdx.x, wid = tid >> 5, lane = tid & 31;
    int wm = wid & 3, wn = wid >> 2;       // 4 x 2 warp grid
    int m0 = wm * 32, n0w = wn * 64;

    extern __shared__ char sm[];
    uint32_t sb = smem_u32(sm);

    const char *pAh, *pAl, *pBh, *pBl;
    if (MODE == 1) {
        pAh = (const char*)(g_xg_hi + (size_t)row0 * HH);
        pAl = (const char*)(g_xg_lo + (size_t)row0 * HH);
        size_t wb = (size_t)e * 2 * II * HH + (size_t)n0 * HH;
        pBh = (const char*)(g_w13i_hi + wb);
        pBl = (const char*)(g_w13i_lo + wb);
    } else {
        pAh = (const char*)(g_h_hi + (size_t)row0 * II);
        pAl = (const char*)(g_h_lo + (size_t)row0 * II);
        size_t wb = (size_t)e * HH * II + (size_t)n0 * II;
        pBh = (const char*)(g_w2t_hi + wb);
        pBl = (const char*)(g_w2t_lo + wb);
    }

    // per-thread auto-advancing load pointers (8): 4 planes x 2 row-groups
    int lrow = tid >> 2, lc16 = tid & 3;
    size_t tho = (size_t)lrow * STRD + (size_t)lc16 * 16;
    const char* gp[8];
    gp[0] = pAh + tho; gp[1] = gp[0] + 64 * STRD;
    gp[2] = pAl + tho; gp[3] = gp[2] + 64 * STRD;
    gp[4] = pBh + tho; gp[5] = gp[4] + 64 * STRD;
    gp[6] = pBl + tho; gp[7] = gp[6] + 64 * STRD;
    // swizzled smem destination offset (row+64 keeps the same swizzle)
    uint32_t dof = (uint32_t)lrow * 64u + (uint32_t)((lc16 ^ ((lrow >> 1) & 3)) * 16);

    auto load_stage = [&](int s) {
        uint32_t dstS = sb + (uint32_t)s * STAGE + dof;
#pragma unroll
        for (int p = 0; p < 4; p++) {
            uint32_t d0 = dstS + p * PLANE;
            asm volatile("cp.async.cg.shared.global [%0], [%1], 16;" :: "r"(d0), "l"(gp[2 * p]));
            asm volatile("cp.async.cg.shared.global [%0], [%1], 16;" :: "r"(d0 + 64 * 64), "l"(gp[2 * p + 1]));
            gp[2 * p]     += 64;
            gp[2 * p + 1] += 64;
        }
        asm volatile("cp.async.commit_group;");
    };

    // fragment address components (swizzle invariant under +16 rows)
    int arow = m0 + (lane & 15);
    int brow = (lane & 7) + ((lane >> 4) << 3);
    uint32_t aswz[2], bswz[2];
#pragma unroll
    for (int sub = 0; sub < 2; sub++) {
        int ca = (lane >> 4) + sub * 2;
        int cb = ((lane >> 3) & 1) + sub * 2;
        aswz[sub] = (uint32_t)arow * 64u + (uint32_t)((ca ^ ((arow >> 1) & 3)) * 16);
        bswz[sub] = (uint32_t)(n0w + brow) * 64u + (uint32_t)((cb ^ ((brow >> 1) & 3)) * 16);
    }

    float acc[16][4];
#pragma unroll
    for (int i = 0; i < 16; i++)
#pragma unroll
        for (int j = 0; j < 4; j++) acc[i][j] = 0.f;

    load_stage(0);
    load_stage(1);

    int cs = 0, fs = 2;
    for (int ks = 0; ks < NK; ks++) {
        if (ks == NK - 1) asm volatile("cp.async.wait_group 0;");
        else              asm volatile("cp.async.wait_group 1;");
        __syncthreads();
        if (ks + 2 < NK) { load_stage(fs); fs = (fs == NSTG - 1) ? 0 : fs + 1; }

        uint32_t base = sb + (uint32_t)cs * STAGE;
        cs = (cs == NSTG - 1) ? 0 : cs + 1;
#pragma unroll
        for (int sub = 0; sub < 2; sub++) {
            uint32_t a0 = base + aswz[sub];
            uint32_t ah[2][4], al[2][4];
            ldmx4(ah[0], a0);
            ldmx4(ah[1], a0 + 16 * 64);
            ldmx4(al[0], a0 + PLANE);
            ldmx4(al[1], a0 + PLANE + 16 * 64);
            uint32_t b0 = base + 2 * PLANE + bswz[sub];
#pragma unroll
            for (int jj = 0; jj < 4; jj++) {
                uint32_t bh[4], bl[4];
                ldmx4(bh, b0 + jj * 1024);
                ldmx4(bl, b0 + PLANE + jj * 1024);
#pragma unroll
                for (int i = 0; i < 2; i++) {
                    mma16816(acc[i * 8 + jj * 2 + 0], ah[i], bh + 0);
                    mma16816(acc[i * 8 + jj * 2 + 1], ah[i], bh + 2);
                }
#pragma unroll
                for (int i = 0; i < 2; i++) {
                    mma16816(acc[i * 8 + jj * 2 + 0], ah[i], bl + 0);
                    mma16816(acc[i * 8 + jj * 2 + 1], ah[i], bl + 2);
                }
#pragma unroll
                for (int i = 0; i < 2; i++) {
                    mma16816(acc[i * 8 + jj * 2 + 0], al[i], bh + 0);
                    mma16816(acc[i * 8 + jj * 2 + 1], al[i], bh + 2);
                }
            }
        }
    }

    // ---------------- epilogue ----------------
    if (MODE == 1) {
        // stage packed (hi,lo) h values in smem (68-word padded rows), then
        // write out coalesced.
        __syncthreads();
        uint32_t* st = (uint32_t*)sm;
        int q = lane & 3;
        int rl = m0 + (lane >> 2);
#pragma unroll
        for (int i = 0; i < 2; i++) {
#pragma unroll
            for (int j = 0; j < 8; j++) {
                const float* c = acc[i * 8 + j];
                int hcl = ((n0w + j * 8) >> 1) + q;
                st[(rl + i * 16)     * 68 + hcl] = pack_h(c[0], c[1]);
                st[(rl + i * 16 + 8) * 68 + hcl] = pack_h(c[2], c[3]);
            }
        }
        __syncthreads();
        int hb = n0 >> 1;
#pragma unroll
        for (int pass = 0; pass < 8; pass++) {
            int r  = pass * 16 + (tid >> 4);
            int c4 = (tid & 15) * 4;
            int grow = row0 + r;
            if (grow < n_end) {
                uint32_t w0 = st[r * 68 + c4 + 0], w1 = st[r * 68 + c4 + 1];
                uint32_t w2 = st[r * 68 + c4 + 2], w3 = st[r * 68 + c4 + 3];
                uint32_t hi0 = (w0 & 0xffffu) | (w1 << 16);
                uint32_t hi1 = (w2 & 0xffffu) | (w3 << 16);
                uint32_t lo0 = (w0 >> 16) | (w1 & 0xffff0000u);
                uint32_t lo1 = (w2 >> 16) | (w3 & 0xffff0000u);
                size_t off = (size_t)grow * II + hb + c4;
                *(uint2*)(g_h_hi + off) = make_uint2(hi0, hi1);
                *(uint2*)(g_h_lo + off) = make_uint2(lo0, lo1);
            }
        }
    } else {
        int rbase = row0 + m0 + (lane >> 2);
        int q     = lane & 3;
#pragma unroll
        for (int i = 0; i < 2; i++) {
            int ra = rbase + i * 16;
#pragma unroll
            for (int j = 0; j < 8; j++) {
                const float* c = acc[i * 8 + j];
                int col = n0 + n0w + j * 8 + 2 * q;
                if (ra < n_end)
                    *(float2*)(g_y + (size_t)ra * HH + col) = make_float2(c[0], c[1]);
                if (ra + 8 < n_end)
                    *(float2*)(g_y + (size_t)(ra + 8) * HH + col) = make_float2(c[2], c[3]);
            }
        }
    }
}

// ---------------- combine: out[t] = sum_k rw[t,k] * y[slot(t,k)] -------------
__global__ __launch_bounds__(256) void k_combine(const float* __restrict__ rw,
                                                 float* __restrict__ out) {
    size_t i = (size_t)blockIdx.x * blockDim.x + threadIdx.x;
    if (i >= (size_t)TT * HH) return;
    int t = (int)(i >> 10);
    int h = (int)(i & 1023);
    int s0 = g_tok_slot[2 * t], s1 = g_tok_slot[2 * t + 1];
    out[i] = rw[2 * t] * g_y[(size_t)s0 * HH + h] + rw[2 * t + 1] * g_y[(size_t)s1 * HH + h];
}

// ---------------- launch -----------------------------------------------------
extern "C" void kernel_launch(void* const* d_in, const int* in_sizes, int n_in,
                              void* d_out, int out_size) {
    const float* x        = (const float*)d_in[0];   // [T,H]
    const int*   routing  = (const int*)  d_in[1];   // [T,K]
    const float* rweights = (const float*)d_in[2];   // [T,K]
    const float* w13      = (const float*)d_in[3];   // [E,H,2I]
    const float* w2       = (const float*)d_in[4];   // [E,I,H]
    float*       out      = (float*)d_out;           // [T,H]

    cudaFuncSetAttribute(k_mma<1>, cudaFuncAttributeMaxDynamicSharedMemorySize, SMEM_BYTES);
    cudaFuncSetAttribute(k_mma<2>, cudaFuncAttributeMaxDynamicSharedMemorySize, SMEM_BYTES);

    // order chosen so launch index 3 (ncu capture slot) is k_mma<1>
    k_route<<<1, 1024>>>(routing);                                 // 0
    k_conv_x<<<TKN, 256>>>(x);                                     // 1
    {
        dim3 g(II / 32, HH / 32, EE);
        k_tconv13<<<g, dim3(32, 8)>>>(w13);                        // 2
    }
    k_mma<1><<<dim3(2 * II / 128, NT_MAX), 256, SMEM_BYTES>>>();   // 3
    {
        dim3 g(HH / 32, II / 32, EE);
        k_tconv2<<<g, dim3(32, 8)>>>(w2);                          // 4
    }
    k_mma<2><<<dim3(HH / 128, NT_MAX), 256, SMEM_BYTES>>>();       // 5
    {
        size_t n = (size_t)TT * HH;
        k_combine<<<(unsigned)((n + 255) / 256), 256>>>(rweights, out);  // 6
    }
}